// round 1
// baseline (speedup 1.0000x reference)
#include <cuda_runtime.h>
#include <math.h>

#define B_  64
#define N_  2048
#define K_  128
#define J_  10
#define D_  16
#define F_  160   // J_*D_

// scratch (device globals: no allocation allowed)
__device__ float g_s [B_*K_];        // sum over n of u
__device__ float g_v [B_*J_*K_];     // v[b,j,k] = sum_d W[k,jd]*o[b,j,d]
__device__ float g_p1[B_*J_*K_];     // p after routing iter 1
__device__ float g_p2[B_*J_*K_];     // p after routing iter 2

__global__ void k_init() {
    int i = blockIdx.x * blockDim.x + threadIdx.x;
    if (i < B_*K_) g_s[i] = 0.f;
    if (i < B_*J_*K_) { g_p1[i] = 0.f; g_p2[i] = 0.f; }
}

// s[b,k] = sum_n u[b,n,k]
__global__ void k_sum(const float* __restrict__ u) {
    int b = blockIdx.y;
    int chunk = blockIdx.x;            // 0..7, 256 rows each
    int k4 = threadIdx.x & 31;         // float4 index within row
    int rg = threadIdx.x >> 5;         // 0..7, 32 rows each
    const float4* up = (const float4*)(u + ((size_t)b*N_ + (size_t)chunk*256 + (size_t)rg*32)*K_);
    float4 acc = make_float4(0.f,0.f,0.f,0.f);
#pragma unroll 8
    for (int r = 0; r < 32; r++) {
        float4 t = up[r*32 + k4];
        acc.x += t.x; acc.y += t.y; acc.z += t.z; acc.w += t.w;
    }
    float* sp = g_s + b*K_ + k4*4;
    atomicAdd(sp+0, acc.x); atomicAdd(sp+1, acc.y);
    atomicAdd(sp+2, acc.z); atomicAdd(sp+3, acc.w);
}

// mode 0: o[b,j,d] = 0.1 * sum_k s[b,k]   * W[k, j*16+d]   (uses g_s)
// mode 1: o[b,j,d] =       sum_k p1[b,j,k]* W[k, j*16+d]   (uses g_p1)
// then    v[b,j,k] = sum_d o[b,j,d] * W[k, j*16+d]
__global__ void k_ov(const float* __restrict__ W, int mode) {
    int b = blockIdx.x, t = threadIdx.x;   // 160 threads
    __shared__ float src[J_*K_];
    __shared__ float so[F_];
    if (mode == 0) {
        if (t < K_) src[t] = g_s[b*K_ + t];
    } else {
        for (int i = t; i < J_*K_; i += F_) src[i] = g_p1[b*J_*K_ + i];
    }
    __syncthreads();
    int j = t >> 4;
    float acc = 0.f;
    const float* wcol = W + t;             // W[k*F_ + t]
    if (mode == 0) {
#pragma unroll 8
        for (int k = 0; k < K_; k++) acc += src[k] * wcol[k*F_];
        acc *= 0.1f;
    } else {
        const float* pj = src + j*K_;
#pragma unroll 8
        for (int k = 0; k < K_; k++) acc += pj[k] * wcol[k*F_];
    }
    so[t] = acc;
    __syncthreads();
    for (int e = t; e < J_*K_; e += F_) {
        int jj = e >> 7, k = e & 127;
        const float* wrow = W + k*F_ + jj*D_;
        const float* oj = so + jj*D_;
        float v = 0.f;
#pragma unroll
        for (int d2 = 0; d2 < D_; d2++) v += oj[d2] * wrow[d2];
        g_v[b*J_*K_ + e] = v;
    }
}

// fused: b[j] = u_row . v[j]  -> softmax over j -> p[j,:] += c[j]*u_row
// 16 lanes per row, 2 rows per warp, p accumulated in registers.
__global__ void __launch_bounds__(256, 2)
k_pass(const float* __restrict__ u, int which) {
    float* p = (which == 0) ? g_p1 : g_p2;
    int b = blockIdx.y;
    int blk = blockIdx.x;                  // 0..7 -> 256 rows each
    __shared__ float sv[J_*K_];
    for (int i = threadIdx.x; i < J_*K_; i += 256) sv[i] = g_v[b*J_*K_ + i];
    __syncthreads();

    int warp = threadIdx.x >> 5, lane = threadIdx.x & 31;
    int half = lane >> 4, l = lane & 15;
    int row0 = blk*256 + warp*32;
    const float* ub = u + (size_t)b*N_*K_;

    float4 pA[J_], pB[J_];
#pragma unroll
    for (int j = 0; j < J_; j++) {
        pA[j] = make_float4(0.f,0.f,0.f,0.f);
        pB[j] = make_float4(0.f,0.f,0.f,0.f);
    }

    for (int it = 0; it < 16; it++) {
        int row = row0 + it*2 + half;
        const float4* ur = (const float4*)(ub + (size_t)row*K_);
        float4 u0 = ur[l*2], u1 = ur[l*2+1];

        float pd[J_];
#pragma unroll
        for (int j = 0; j < J_; j++) {
            const float4* vj = (const float4*)(sv + j*K_);
            float4 v0 = vj[l*2], v1 = vj[l*2+1];
            pd[j] = u0.x*v0.x + u0.y*v0.y + u0.z*v0.z + u0.w*v0.w
                  + u1.x*v1.x + u1.y*v1.y + u1.z*v1.z + u1.w*v1.w;
        }
        // reduce across the 16 lanes owning this row
#pragma unroll
        for (int m = 8; m >= 1; m >>= 1) {
#pragma unroll
            for (int j = 0; j < J_; j++)
                pd[j] += __shfl_xor_sync(0xffffffffu, pd[j], m);
        }
        // softmax over j (10 values, all lanes have them)
        float mx = pd[0];
#pragma unroll
        for (int j = 1; j < J_; j++) mx = fmaxf(mx, pd[j]);
        float Z = 0.f;
#pragma unroll
        for (int j = 0; j < J_; j++) { pd[j] = __expf(pd[j] - mx); Z += pd[j]; }
        float rZ = 1.0f / Z;
#pragma unroll
        for (int j = 0; j < J_; j++) {
            float c = pd[j] * rZ;
            pA[j].x += c*u0.x; pA[j].y += c*u0.y; pA[j].z += c*u0.z; pA[j].w += c*u0.w;
            pB[j].x += c*u1.x; pB[j].y += c*u1.y; pB[j].z += c*u1.z; pB[j].w += c*u1.w;
        }
    }

    // fold the two half-warps (same k-slice, different rows)
#pragma unroll
    for (int j = 0; j < J_; j++) {
        pA[j].x += __shfl_xor_sync(0xffffffffu, pA[j].x, 16);
        pA[j].y += __shfl_xor_sync(0xffffffffu, pA[j].y, 16);
        pA[j].z += __shfl_xor_sync(0xffffffffu, pA[j].z, 16);
        pA[j].w += __shfl_xor_sync(0xffffffffu, pA[j].w, 16);
        pB[j].x += __shfl_xor_sync(0xffffffffu, pB[j].x, 16);
        pB[j].y += __shfl_xor_sync(0xffffffffu, pB[j].y, 16);
        pB[j].z += __shfl_xor_sync(0xffffffffu, pB[j].z, 16);
        pB[j].w += __shfl_xor_sync(0xffffffffu, pB[j].w, 16);
    }
    if (half == 0) {
        float* pb = p + b*J_*K_;
#pragma unroll
        for (int j = 0; j < J_; j++) {
            float* dst = pb + j*K_ + l*8;
            atomicAdd(dst+0, pA[j].x); atomicAdd(dst+1, pA[j].y);
            atomicAdd(dst+2, pA[j].z); atomicAdd(dst+3, pA[j].w);
            atomicAdd(dst+4, pB[j].x); atomicAdd(dst+5, pB[j].y);
            atomicAdd(dst+6, pB[j].z); atomicAdd(dst+7, pB[j].w);
        }
    }
}

// o2[b,j,d] = sum_k p2[b,j,k]*W[k,jd]; out = squash(o2) over d
__global__ void k_final(const float* __restrict__ W, float* __restrict__ out) {
    int b = blockIdx.x, t = threadIdx.x;   // 160 threads
    int j = t >> 4;
    __shared__ float so[F_];
    const float* pj = g_p2 + b*J_*K_ + j*K_;
    const float* wcol = W + t;
    float acc = 0.f;
#pragma unroll 8
    for (int k = 0; k < K_; k++) acc += pj[k] * wcol[k*F_];
    so[t] = acc;
    __syncthreads();
    float s2 = 0.f;
#pragma unroll
    for (int d2 = 0; d2 < D_; d2++) { float x = so[j*D_ + d2]; s2 += x*x; }
    out[b*F_ + t] = acc * s2 / ((1.f + s2) * sqrtf(s2 + 1e-7f));
}

extern "C" void kernel_launch(void* const* d_in, const int* in_sizes, int n_in,
                              void* d_out, int out_size) {
    const float* u = (const float*)d_in[0];
    const float* W = (const float*)d_in[1];
    float* out = (float*)d_out;

    k_init<<<(B_*J_*K_ + 255)/256, 256>>>();
    k_sum<<<dim3(8, B_), 256>>>(u);
    k_ov<<<B_, F_>>>(W, 0);                 // o0 (c uniform), v1
    k_pass<<<dim3(8, B_), 256>>>(u, 0);     // b1 -> softmax -> p1
    k_ov<<<B_, F_>>>(W, 1);                 // o1, v2
    k_pass<<<dim3(8, B_), 256>>>(u, 1);     // b2 -> softmax -> p2
    k_final<<<B_, F_>>>(W, out);            // o2 -> squash
}

// round 2
// speedup vs baseline: 1.3494x; 1.3494x over previous
#include <cuda_runtime.h>
#include <math.h>

#define B_  64
#define N_  2048
#define K_  128
#define J_  10
#define D_  16
#define F_  160   // J_*D_

typedef unsigned long long u64;

// scratch (device globals: no allocation allowed)
__device__ float g_s [B_*K_];        // sum over n of u
__device__ float g_v [B_*J_*K_];     // v[b,j,k] = sum_d W[k,jd]*o[b,j,d]
__device__ float g_p1[B_*J_*K_];     // p after routing iter 1
__device__ float g_p2[B_*J_*K_];     // p after routing iter 2

__device__ __forceinline__ u64 ffma2(u64 a, u64 b, u64 c) {
    u64 d; asm("fma.rn.f32x2 %0, %1, %2, %3;" : "=l"(d) : "l"(a), "l"(b), "l"(c));
    return d;
}
__device__ __forceinline__ u64 pack2(float x, float y) {
    u64 d; asm("mov.b64 %0, {%1, %2};" : "=l"(d) : "f"(x), "f"(y));
    return d;
}
__device__ __forceinline__ float2 unpack2(u64 v) {
    float2 r; asm("mov.b64 {%0, %1}, %2;" : "=f"(r.x), "=f"(r.y) : "l"(v));
    return r;
}

__global__ void k_init() {
    int i = blockIdx.x * blockDim.x + threadIdx.x;
    if (i < B_*K_) g_s[i] = 0.f;
    if (i < B_*J_*K_) { g_p1[i] = 0.f; g_p2[i] = 0.f; }
}

// s[b,k] = sum_n u[b,n,k]
__global__ void k_sum(const float* __restrict__ u) {
    int b = blockIdx.y;
    int chunk = blockIdx.x;            // 0..7, 256 rows each
    int k4 = threadIdx.x & 31;         // float4 index within row
    int rg = threadIdx.x >> 5;         // 0..7, 32 rows each
    const float4* up = (const float4*)(u + ((size_t)b*N_ + (size_t)chunk*256 + (size_t)rg*32)*K_);
    float4 acc = make_float4(0.f,0.f,0.f,0.f);
#pragma unroll 8
    for (int r = 0; r < 32; r++) {
        float4 t = up[r*32 + k4];
        acc.x += t.x; acc.y += t.y; acc.z += t.z; acc.w += t.w;
    }
    float* sp = g_s + b*K_ + k4*4;
    atomicAdd(sp+0, acc.x); atomicAdd(sp+1, acc.y);
    atomicAdd(sp+2, acc.z); atomicAdd(sp+3, acc.w);
}

// mode 0: o[b,j,d] = 0.1 * sum_k s[b,k]   * W[k, j*16+d]   (uses g_s)
// mode 1: o[b,j,d] =       sum_k p1[b,j,k]* W[k, j*16+d]   (uses g_p1)
// then    v[b,j,k] = sum_d o[b,j,d] * W[k, j*16+d]
__global__ void k_ov(const float* __restrict__ W, int mode) {
    int b = blockIdx.x, t = threadIdx.x;   // 160 threads
    __shared__ float src[J_*K_];
    __shared__ float so[F_];
    if (mode == 0) {
        if (t < K_) src[t] = g_s[b*K_ + t];
    } else {
        for (int i = t; i < J_*K_; i += F_) src[i] = g_p1[b*J_*K_ + i];
    }
    __syncthreads();
    int j = t >> 4;
    float acc = 0.f;
    const float* wcol = W + t;             // W[k*F_ + t]
    if (mode == 0) {
#pragma unroll 8
        for (int k = 0; k < K_; k++) acc += src[k] * wcol[k*F_];
        acc *= 0.1f;
    } else {
        const float* pj = src + j*K_;
#pragma unroll 8
        for (int k = 0; k < K_; k++) acc += pj[k] * wcol[k*F_];
    }
    so[t] = acc;
    __syncthreads();
    for (int e = t; e < J_*K_; e += F_) {
        int jj = e >> 7, k = e & 127;
        const float* wrow = W + k*F_ + jj*D_;
        const float* oj = so + jj*D_;
        float v = 0.f;
#pragma unroll
        for (int d2 = 0; d2 < D_; d2++) v += oj[d2] * wrow[d2];
        g_v[b*J_*K_ + e] = v;
    }
}

// fused: b[j] = u_row . v[j]  -> softmax over j -> p[j,:] += c[j]*u_row
// dot phase: 16 lanes per row (2 rows per warp), packed f32x2 math.
// accum phase: full-warp k-spread (lane owns 4 k's) -> p regs = 40, not 80.
__global__ void __launch_bounds__(256, 3)
k_pass(const float* __restrict__ u, int which) {
    float* p = (which == 0) ? g_p1 : g_p2;
    int b = blockIdx.y;
    int blk = blockIdx.x;                  // 0..7 -> 256 rows each
    // v staged with a bank-conflict-free permutation:
    // float (j,k) stored at j*128 + ((k>>2)&1)*64 + (k>>3)*4 + (k&3)
    __shared__ float sv[J_*K_];
    for (int i = threadIdx.x; i < J_*K_; i += 256) {
        int j = i >> 7, k = i & 127;
        int pos = j*K_ + (((k>>2)&1)<<6) + ((k>>3)<<2) + (k&3);
        sv[pos] = g_v[b*J_*K_ + i];
    }
    __syncthreads();

    int warp = threadIdx.x >> 5, lane = threadIdx.x & 31;
    int half = lane >> 4, l = lane & 15;
    int base0 = blk*256 + warp*32;
    const float* ub = u + (size_t)b*N_*K_;

    u64 p2[J_][2];
#pragma unroll
    for (int j = 0; j < J_; j++) { p2[j][0] = 0ULL; p2[j][1] = 0ULL; }

    for (int it = 0; it < 16; it++) {
        int rA = base0 + it*2;
        // accumulation-phase loads (32-lane k-spread) issued early to hide latency
        const u64* uA = (const u64*)(ub + (size_t)rA*K_);
        const u64* uB = (const u64*)(ub + (size_t)(rA+1)*K_);
        u64 a0 = uA[lane*2], a1 = uA[lane*2+1];
        u64 b0 = uB[lane*2], b1 = uB[lane*2+1];
        // dot-phase loads: this lane's 8-float slice of row rA+half
        const ulonglong2* ur = (const ulonglong2*)(ub + (size_t)(rA+half)*K_ + l*8);
        ulonglong2 q0 = ur[0], q1 = ur[1];

        float pd[J_];
#pragma unroll
        for (int j = 0; j < J_; j++) {
            ulonglong2 v0 = *(const ulonglong2*)(sv + j*K_ + l*4);
            ulonglong2 v1 = *(const ulonglong2*)(sv + j*K_ + 64 + l*4);
            u64 acc = ffma2(q0.x, v0.x, 0ULL);
            acc = ffma2(q0.y, v0.y, acc);
            acc = ffma2(q1.x, v1.x, acc);
            acc = ffma2(q1.y, v1.y, acc);
            float2 f = unpack2(acc);
            pd[j] = f.x + f.y;
        }
        // reduce across the 16 lanes owning this row
#pragma unroll
        for (int m = 8; m >= 1; m >>= 1) {
#pragma unroll
            for (int j = 0; j < J_; j++)
                pd[j] += __shfl_xor_sync(0xffffffffu, pd[j], m);
        }
        // softmax over j (each half holds its own row's dots)
        float m01 = fmaxf(pd[0], pd[1]), m23 = fmaxf(pd[2], pd[3]);
        float m45 = fmaxf(pd[4], pd[5]), m67 = fmaxf(pd[6], pd[7]);
        float m89 = fmaxf(pd[8], pd[9]);
        float mx = fmaxf(fmaxf(fmaxf(m01, m23), fmaxf(m45, m67)), m89);
        float Z = 0.f;
#pragma unroll
        for (int j = 0; j < J_; j++) { pd[j] = __expf(pd[j] - mx); Z += pd[j]; }
        float rZ = __fdividef(1.0f, Z);
        // accumulate both rows with full-warp k-spread
#pragma unroll
        for (int j = 0; j < J_; j++) {
            float cOwn = pd[j] * rZ;
            float cOth = __shfl_xor_sync(0xffffffffu, cOwn, 16);
            float cA = half ? cOth : cOwn;
            float cB = half ? cOwn : cOth;
            u64 cA2 = pack2(cA, cA);
            u64 cB2 = pack2(cB, cB);
            p2[j][0] = ffma2(cA2, a0, p2[j][0]);
            p2[j][1] = ffma2(cA2, a1, p2[j][1]);
            p2[j][0] = ffma2(cB2, b0, p2[j][0]);
            p2[j][1] = ffma2(cB2, b1, p2[j][1]);
        }
    }

    float* pb = p + b*J_*K_ + lane*4;
#pragma unroll
    for (int j = 0; j < J_; j++) {
        float2 x0 = unpack2(p2[j][0]);
        float2 x1 = unpack2(p2[j][1]);
        atomicAdd(pb + j*K_ + 0, x0.x);
        atomicAdd(pb + j*K_ + 1, x0.y);
        atomicAdd(pb + j*K_ + 2, x1.x);
        atomicAdd(pb + j*K_ + 3, x1.y);
    }
}

// o2[b,j,d] = sum_k p2[b,j,k]*W[k,jd]; out = squash(o2) over d
__global__ void k_final(const float* __restrict__ W, float* __restrict__ out) {
    int b = blockIdx.x, t = threadIdx.x;   // 160 threads
    int j = t >> 4;
    __shared__ float so[F_];
    const float* pj = g_p2 + b*J_*K_ + j*K_;
    const float* wcol = W + t;
    float acc = 0.f;
#pragma unroll 8
    for (int k = 0; k < K_; k++) acc += pj[k] * wcol[k*F_];
    so[t] = acc;
    __syncthreads();
    float s2 = 0.f;
#pragma unroll
    for (int d2 = 0; d2 < D_; d2++) { float x = so[j*D_ + d2]; s2 += x*x; }
    out[b*F_ + t] = acc * s2 / ((1.f + s2) * sqrtf(s2 + 1e-7f));
}

extern "C" void kernel_launch(void* const* d_in, const int* in_sizes, int n_in,
                              void* d_out, int out_size) {
    const float* u = (const float*)d_in[0];
    const float* W = (const float*)d_in[1];
    float* out = (float*)d_out;

    k_init<<<(B_*J_*K_ + 255)/256, 256>>>();
    k_sum<<<dim3(8, B_), 256>>>(u);
    k_ov<<<B_, F_>>>(W, 0);                 // o0 (c uniform), v1
    k_pass<<<dim3(8, B_), 256>>>(u, 0);     // b1 -> softmax -> p1
    k_ov<<<B_, F_>>>(W, 1);                 // o1, v2
    k_pass<<<dim3(8, B_), 256>>>(u, 1);     // b2 -> softmax -> p2
    k_final<<<B_, F_>>>(W, out);            // o2 -> squash
}